// round 1
// baseline (speedup 1.0000x reference)
#include <cuda_runtime.h>
#include <cstdint>
#include <cstddef>

// Problem constants
#define Bq 8
#define Nq 4096
#define Pq 4096
#define Kq 32
#define Cq 128
#define Wq 16
#define EPSq 1e-5f

#define TPT 16                      // points per block in main kernel
#define NBLK ((Bq * Pq) / TPT)      // 2048 blocks

// Scratch (static device globals; no allocation allowed)
__device__ float g_Ap[4 * Cq * Cq];              // A'[d][c][j], 256 KB
__device__ float g_Y[(size_t)Bq * Pq * Cq];      // pre-LN activations (b,p,j), 16 MB
__device__ float g_ps[NBLK * Cq];                // per-block partial sums
__device__ float g_pq[NBLK * Cq];                // per-block partial sumsq
__device__ float g_scale[Cq];
__device__ float g_shift[Cq];

// ---- packed f32x2 helpers (Blackwell sm_103a) ----
__device__ __forceinline__ unsigned long long pk2(float x, float y) {
    unsigned long long r;
    asm("mov.b64 %0, {%1,%2};" : "=l"(r) : "f"(x), "f"(y));
    return r;
}
__device__ __forceinline__ void fma2(unsigned long long& d,
                                     unsigned long long a,
                                     unsigned long long b) {
    asm("fma.rn.f32x2 %0, %1, %2, %0;" : "+l"(d) : "l"(a), "l"(b));
}
__device__ __forceinline__ float2 up2(unsigned long long v) {
    float x, y;
    asm("mov.b64 {%0,%1}, %2;" : "=f"(x), "=f"(y) : "l"(v));
    return make_float2(x, y);
}

// ============================================================
// Kernel A: precompute A'[d,c,j] = sum_w Ww[d,w]*Wl[c*16+w, j]
//           (d==3 row uses bw[w] instead of Ww)
// ============================================================
__global__ void prep_kernel(const float* __restrict__ Ww,
                            const float* __restrict__ bw,
                            const float* __restrict__ Wl) {
    int idx = blockIdx.x * blockDim.x + threadIdx.x;
    if (idx >= 4 * Cq * Cq) return;
    int d = idx >> 14;
    int c = (idx >> 7) & (Cq - 1);
    int j = idx & (Cq - 1);
    float acc = 0.f;
#pragma unroll
    for (int w = 0; w < Wq; w++) {
        float coef = (d < 3) ? Ww[d * Wq + w] : bw[w];
        acc = fmaf(coef, Wl[(c * Wq + w) * Cq + j], acc);
    }
    g_Ap[idx] = acc;
}

// ============================================================
// Kernel B: main fused kernel.
//   per point p (source batch s = data_idx[b]):
//     S[d,c] = sum_k coef[k,d] * points[s, nbr[k], c]
//     y[j]   = sum_{d,c} S[d,c] * A'[d,c,j] + bl[j]
//   writes g_Y and per-block LN partial sums.
// ============================================================
__global__ __launch_bounds__(128, 4) void main_kernel(
    const float* __restrict__ points,
    const float* __restrict__ lc,
    const int* __restrict__ nbr,
    const int* __restrict__ didx,
    const float* __restrict__ bl) {
    __shared__ int s_nbr[TPT][Kq];
    __shared__ __align__(16) ulonglong2 s_L[TPT][Kq];     // {pk2(L0,L1), pk2(L2,1)}
    __shared__ __align__(16) float s_S[TPT][4 * Cq];

    const int tid = threadIdx.x;
    const int blk = blockIdx.x;
    const int b = blk / (Pq / TPT);
    const int chunk = blk % (Pq / TPT);
    const int p0 = chunk * TPT;
    const int src = didx[b];
    const float* pts = points + (size_t)src * Nq * Cq;
    const size_t base = ((size_t)src * Pq + p0) * Kq;

    // cooperative load of neighbor lists + local coords (pre-packed)
    for (int i = tid; i < TPT * Kq; i += 128) {
        int t = i >> 5, k = i & 31;
        s_nbr[t][k] = nbr[base + (size_t)t * Kq + k];
        const float* Lp = lc + (base + (size_t)t * Kq + k) * 3;
        float l0 = Lp[0], l1 = Lp[1], l2 = Lp[2];
        s_L[t][k] = make_ulonglong2(pk2(l0, l1), pk2(l2, 1.0f));
    }
    __syncthreads();

    // ---- stage 1: thread owns channel c = tid ----
    for (int t = 0; t < TPT; t++) {
        unsigned long long a01 = 0ull, a23 = 0ull;   // {S0,S1}, {S2,S3}
#pragma unroll 8
        for (int k = 0; k < Kq; k++) {
            float v = pts[(size_t)s_nbr[t][k] * Cq + tid];
            unsigned long long v2 = pk2(v, v);
            ulonglong2 L = s_L[t][k];
            fma2(a01, v2, L.x);
            fma2(a23, v2, L.y);
        }
        float2 f01 = up2(a01), f23 = up2(a23);
        s_S[t][0 * Cq + tid] = f01.x;
        s_S[t][1 * Cq + tid] = f01.y;
        s_S[t][2 * Cq + tid] = f23.x;
        s_S[t][3 * Cq + tid] = f23.y;
    }
    __syncthreads();

    // ---- stage 2: thread owns output channel j = tid ----
    unsigned long long acc[TPT];
#pragma unroll
    for (int t = 0; t < TPT; t++) acc[t] = 0ull;
    const float* Apj = g_Ap + tid;
    for (int i = 0; i < 4 * Cq; i += 4) {
        float a0 = Apj[(i + 0) * Cq];
        float a1 = Apj[(i + 1) * Cq];
        float a2 = Apj[(i + 2) * Cq];
        float a3 = Apj[(i + 3) * Cq];
        unsigned long long a01 = pk2(a0, a1);
        unsigned long long a23 = pk2(a2, a3);
#pragma unroll
        for (int t = 0; t < TPT; t++) {
            ulonglong2 s = *reinterpret_cast<const ulonglong2*>(&s_S[t][i]);
            fma2(acc[t], s.x, a01);
            fma2(acc[t], s.y, a23);
        }
    }

    const float blj = bl[tid];
    float lsum = 0.f, lsq = 0.f;
#pragma unroll
    for (int t = 0; t < TPT; t++) {
        float2 f = up2(acc[t]);
        float y = f.x + f.y + blj;
        g_Y[((size_t)b * Pq + p0 + t) * Cq + tid] = y;
        lsum += y;
        lsq += y * y;
    }
    g_ps[(size_t)blk * Cq + tid] = lsum;
    g_pq[(size_t)blk * Cq + tid] = lsq;
}

// ============================================================
// Kernel S2: deterministic fixed-order reduction of partials,
// produce per-channel scale/shift.
// ============================================================
__global__ void stats_kernel(const float* __restrict__ gamma,
                             const float* __restrict__ beta) {
    int j = threadIdx.x;  // 128 threads
    float s0 = 0.f, s1 = 0.f, s2 = 0.f, s3 = 0.f;
    float q0 = 0.f, q1 = 0.f, q2 = 0.f, q3 = 0.f;
    for (int i = 0; i < NBLK; i += 4) {
        s0 += g_ps[(i + 0) * Cq + j];
        s1 += g_ps[(i + 1) * Cq + j];
        s2 += g_ps[(i + 2) * Cq + j];
        s3 += g_ps[(i + 3) * Cq + j];
        q0 += g_pq[(i + 0) * Cq + j];
        q1 += g_pq[(i + 1) * Cq + j];
        q2 += g_pq[(i + 2) * Cq + j];
        q3 += g_pq[(i + 3) * Cq + j];
    }
    float s = (s0 + s1) + (s2 + s3);
    float q = (q0 + q1) + (q2 + q3);
    const float inv = 1.0f / (float)(Bq * Pq);
    float mean = s * inv;
    float var = q * inv - mean * mean;
    float sc = rsqrtf(var + EPSq) * gamma[j];
    g_scale[j] = sc;
    g_shift[j] = beta[j] - mean * sc;
}

// ============================================================
// Kernel C: LN + relu + (b,p,j) -> (b,j,p) transpose via smem tile
// ============================================================
__global__ __launch_bounds__(256) void out_kernel(float* __restrict__ out) {
    __shared__ float tile[32][33];
    const int tx = threadIdx.x & 31;
    const int ty = threadIdx.x >> 5;  // 0..7
    const int b = blockIdx.z;
    const int jt = blockIdx.y;   // 0..3
    const int pt = blockIdx.x;   // 0..127

    const int j = jt * 32 + tx;
    const float sc = g_scale[j];
    const float sh = g_shift[j];
#pragma unroll
    for (int r = 0; r < 4; r++) {
        int p = pt * 32 + ty + r * 8;
        float v = g_Y[((size_t)b * Pq + p) * Cq + j];
        tile[ty + r * 8][tx] = fmaxf(fmaf(v, sc, sh), 0.f);
    }
    __syncthreads();
#pragma unroll
    for (int r = 0; r < 4; r++) {
        int jj = jt * 32 + ty + r * 8;
        out[((size_t)b * Cq + jj) * Pq + pt * 32 + tx] = tile[tx][ty + r * 8];
    }
}

// ============================================================
// Launch
// ============================================================
extern "C" void kernel_launch(void* const* d_in, const int* in_sizes, int n_in,
                              void* d_out, int out_size) {
    const float* xyz    = (const float*)d_in[0];
    const float* points = (const float*)d_in[1];
    const float* lc     = (const float*)d_in[2];
    const int*   nbr    = (const int*)d_in[3];
    const int*   didx   = (const int*)d_in[4];
    const float* Ww     = (const float*)d_in[5];
    const float* bw     = (const float*)d_in[6];
    const float* Wl     = (const float*)d_in[7];
    const float* bl     = (const float*)d_in[8];
    const float* gamma  = (const float*)d_in[9];
    const float* beta   = (const float*)d_in[10];
    float* out = (float*)d_out;

    // xyz passthrough (first tuple element)
    cudaMemcpyAsync(out, xyz, (size_t)Bq * Pq * 3 * sizeof(float),
                    cudaMemcpyDeviceToDevice, 0);

    prep_kernel<<<256, 256>>>(Ww, bw, Wl);
    main_kernel<<<NBLK, 128>>>(points, lc, nbr, didx, bl);
    stats_kernel<<<1, Cq>>>(gamma, beta);

    dim3 g(Pq / 32, Cq / 32, Bq);
    out_kernel<<<g, 256>>>(out + (size_t)Bq * Pq * 3);
}